// round 17
// baseline (speedup 1.0000x reference)
#include <cuda_runtime.h>
#include <stdint.h>

#define RNODES 256
#define LUT_LEN 262144            // 2^18 entries per node
#define LUT_WORDS 8192            // 2^18 / 32
#define NSTEP 512
#define NSAMP 512
#define NIN 32
#define NOUT 10

// 13-bit groups: 19 full (g=0..18, bits 13g..13g+12, covering k=0..246)
// + one 9-bit tail (k=247..255). Row layout: [g][c13] then [tail c9].
#define NG13 19
#define TAB13_TAIL (NG13 * 8192)        // 155648
#define TAB13_ROWS (TAB13_TAIL + 512)   // 156160 rows x 128 u32-pairs = 80 MB

// Half tables for building tab13: A = low 6 bits of each group, B = high 7.
#define TA_N (NG13 * 64 * RNODES)       // 311296
#define TB_N (NG13 * 128 * RNODES)      // 622592
#define TT_N (512 * RNODES)             // 131072 (9-bit tail)

// Static device scratch (allocation-free rule).
__device__ uint32_t g_lutbits[RNODES * LUT_WORDS];   // 8 MB bit-packed LUT (L2)
__device__ uint16_t g_tabA[TA_N];                    // 6-bit halves
__device__ uint16_t g_tabB[TB_N];                    // 7-bit halves
__device__ uint16_t g_tabT[TT_N];                    // 9-bit tail combos
__device__ uint32_t g_tab13[TAB13_ROWS * 128];       // 80 MB pair table (L2)
__device__ uint32_t g_xpack[NSAMP * NSTEP];          // per (m,s): 32 input bits
__device__ int      g_inv[RNODES];                   // node -> input slot, or -1
__device__ int      g_init[RNODES];                  // initial state bits
__device__ int      g_mode;                          // bool enc: 0=i32 1=u8 2=f32

__device__ __forceinline__ int read_bool(const void* p, long i, int mode) {
    if (mode == 0) return ((const int*)p)[i] != 0;
    if (mode == 1) return ((const unsigned char*)p)[i] != 0;
    return ((const float*)p)[i] != 0.0f;
}

__global__ void detect_kernel(const uint32_t* __restrict__ xw) {
    int lane = threadIdx.x;
    if (blockIdx.x || lane >= 32) return;
    int isf = 0, big = 0;
    for (int i = 0; i < 32; i++) {
        uint32_t v = xw[i * 32 + lane];
        if (v == 0x3f800000u) isf = 1;
        if (v > 1u) big = 1;
    }
    unsigned af = __ballot_sync(0xffffffffu, isf);
    unsigned ab = __ballot_sync(0xffffffffu, big);
    if (lane == 0) g_mode = af ? 2 : (ab ? 1 : 0);
}

// Warp-ballot LUT pack: fully coalesced 268 MB stream (DRAM-bound).
__global__ void pack_lut_kernel(const int* __restrict__ lut) {
    int gwarp = (blockIdx.x * blockDim.x + threadIdx.x) >> 5;
    int lane  = threadIdx.x & 31;
    const int* base = lut + (size_t)gwarp * 1024;
    uint32_t mine = 0;
#pragma unroll
    for (int w = 0; w < 32; w++) {
        int v = base[w * 32 + lane];
        unsigned m = __ballot_sync(0xffffffffu, v & 1);
        if (lane == w) mine = m;
    }
    g_lutbits[(size_t)gwarp * 32 + lane] = mine;
}

// Warp-ballot x pack: 262144 words / 32 per warp = 8192 warps.
__global__ void pack_x_kernel(const void* __restrict__ x) {
    int gwarp = (blockIdx.x * blockDim.x + threadIdx.x) >> 5;
    int lane  = threadIdx.x & 31;
    int mode  = g_mode;
    long base = (long)gwarp * 1024;
    uint32_t mine = 0;
#pragma unroll
    for (int w = 0; w < 32; w++) {
        int v = read_bool(x, base + w * 32 + lane, mode);
        unsigned m = __ballot_sync(0xffffffffu, v);
        if (lane == w) mine = m;
    }
    g_xpack[gwarp * 32 + lane] = mine;
}

// misc (inv/init) + 6-bit A halves + 7-bit B halves + 9-bit tail combos
#define SEC_MISC RNODES
__global__ void prep_small_kernel(const int* __restrict__ input_nodes,
                                  const void* __restrict__ init_res,
                                  const void* __restrict__ W,
                                  const int* __restrict__ primes) {
    int i = blockIdx.x * blockDim.x + threadIdx.x;
    int mode = g_mode;
    if (i < SEC_MISC) {
        int inv = -1;
#pragma unroll
        for (int q = 0; q < NIN; q++)
            if (input_nodes[q] == i) inv = q;
        g_inv[i] = inv;
        g_init[i] = read_bool(init_res, i, mode);
    }
    i -= SEC_MISC;
    if (i >= 0 && i < TA_N) {
        // tabA entry (g, c6, node): bits j=0..5 -> k = 13g + j
        int node = i & 255;
        int c    = (i >> 8) & 63;
        int g    = i >> 14;
        uint32_t sum = 0;
#pragma unroll
        for (int j = 0; j < 6; j++) {
            if (c & (1 << j)) {
                int k = 13 * g + j;
                if (read_bool(W, (long)node * RNODES + k, mode))
                    sum += (uint32_t)primes[k];
            }
        }
        g_tabA[i] = (uint16_t)sum;
        return;
    }
    i -= TA_N;
    if (i >= 0 && i < TB_N) {
        // tabB entry (g, c7, node): bits j=0..6 -> k = 13g + 6 + j
        int node = i & 255;
        int c    = (i >> 8) & 127;
        int g    = i >> 15;
        uint32_t sum = 0;
#pragma unroll
        for (int j = 0; j < 7; j++) {
            if (c & (1 << j)) {
                int k = 13 * g + 6 + j;
                if (read_bool(W, (long)node * RNODES + k, mode))
                    sum += (uint32_t)primes[k];
            }
        }
        g_tabB[i] = (uint16_t)sum;
        return;
    }
    i -= TB_N;
    if (i >= 0 && i < TT_N) {
        // tail entry (c9, node): bits j=0..8 -> k = 247 + j
        int node = i & 255;
        int c    = i >> 8;
        uint32_t sum = 0;
#pragma unroll
        for (int j = 0; j < 9; j++) {
            if (c & (1 << j)) {
                int k = 247 + j;
                if (read_bool(W, (long)node * RNODES + k, mode))
                    sum += (uint32_t)primes[k];
            }
        }
        g_tabT[i] = (uint16_t)sum;
    }
}

// Build paired 13-bit table (write-bound, 80 MB).
// Entry (row, t): u16 pair {node t, node t+128}.
__global__ void prep2_kernel() {
    int i = blockIdx.x * blockDim.x + threadIdx.x;
    if (i >= TAB13_ROWS * 128) return;
    int t   = i & 127;
    int row = i >> 7;
    uint32_t lo, hi;
    if (row < TAB13_TAIL) {
        int g  = row >> 13;
        int c  = row & 8191;
        int rA = (g * 64 + (c & 63)) * RNODES;
        int rB = (g * 128 + (c >> 6)) * RNODES;
        lo = (uint32_t)g_tabA[rA + t]       + (uint32_t)g_tabB[rB + t];
        hi = (uint32_t)g_tabA[rA + t + 128] + (uint32_t)g_tabB[rB + t + 128];
    } else {
        int c9 = row - TAB13_TAIL;                // k = 247..255 combos
        lo = g_tabT[c9 * RNODES + t];
        hi = g_tabT[c9 * RNODES + t + 128];
    }
    g_tab13[i] = lo | (hi << 16);
}

// 512 CTAs x 128 threads. CTA = one sample; thread t owns nodes t and t+128
// (packed u16 accumulation). Structure VERBATIM R8; only the group width
// changed: 19 x 13-bit groups + 9-bit tail -> 20 coalesced LDG.32 per step.
__global__ void __launch_bounds__(128, 4)
reservoir_kernel(const float* __restrict__ roW,
                 const float* __restrict__ rob,
                 float* __restrict__ out) {
    __shared__ uint32_t sh_xw[NSTEP];
    __shared__ uint32_t sh_r[16];       // 2 bufs * 8 mask words
    __shared__ float    sh_bits[RNODES];

    const int t    = threadIdx.x;       // 0..127
    const int w    = t >> 5;
    const int lane = t & 31;
    const int sid  = blockIdx.x;

    for (int i = t; i < NSTEP; i += 128)
        sh_xw[i] = g_xpack[sid * NSTEP + i];

    const int inv0 = g_inv[t];
    const int inv1 = g_inv[t + 128];
    unsigned b0 = (unsigned)g_init[t];
    unsigned b1 = (unsigned)g_init[t + 128];

    __syncthreads();

    for (int s = 0; s < NSTEP; s++) {
        // 1) input override (before the matvec, as in the reference)
        uint32_t xw = sh_xw[s];
        unsigned a0 = (inv0 >= 0) ? ((xw >> inv0) & 1u) : b0;
        unsigned a1 = (inv1 >= 0) ? ((xw >> inv1) & 1u) : b1;

        // 2) state bitmask words: warp w -> words w and w+4
        unsigned m0 = __ballot_sync(0xffffffffu, a0);
        unsigned m1 = __ballot_sync(0xffffffffu, a1);
        uint32_t* rb = sh_r + (s & 1) * 8;
        if (lane == 0) { rb[w] = m0; rb[w + 4] = m1; }
        __syncthreads();

        uint4 ra  = *(const uint4*)(rb);
        uint4 rb4 = *(const uint4*)(rb + 4);
        uint32_t wv[8] = {ra.x, ra.y, ra.z, ra.w, rb4.x, rb4.y, rb4.z, rb4.w};

        // 3) 13-bit-group pair sums: 20 independent coalesced LDG.32
        uint32_t i0 = 0, i1 = 0;
#pragma unroll
        for (int trip = 0; trip < 6; trip++) {
            uint32_t acc = 0;   // packed u16; 3 groups max < 62.4K
#pragma unroll
            for (int j = 0; j < 3; j++) {
                int g  = trip * 3 + j;               // 0..17
                int bp = 13 * g;
                int wi = bp >> 5, sh = bp & 31;
                uint32_t c = __funnelshift_r(wv[wi], wv[(wi + 1) & 7], sh) & 0x1FFFu;
                acc = __vadd2(acc, g_tab13[((uint32_t)g << 20) + (c << 7) + t]);
            }
            i0 += acc & 0xFFFFu;
            i1 += acc >> 16;
        }
        {   // trip 6: group 18 (bits 234..246) + 9-bit tail (bits 247..255)
            uint32_t c18 = (wv[7] >> 10) & 0x1FFFu;
            uint32_t c9  = wv[7] >> 23;
            uint32_t acc = g_tab13[(18u << 20) + (c18 << 7) + t];
            acc = __vadd2(acc, g_tab13[(((uint32_t)TAB13_TAIL + c9) << 7) + t]);
            i0 += acc & 0xFFFFu;      // max 20.8K + 14.5K < 65536
            i1 += acc >> 16;
        }

        // 4) bit-packed LUT gather (8 MB, L2-resident)
        uint32_t w0 = g_lutbits[((uint32_t)t << 13)         + (i0 >> 5)];
        uint32_t w1 = g_lutbits[((uint32_t)(t + 128) << 13) + (i1 >> 5)];
        b0 = (w0 >> (i0 & 31u)) & 1u;
        b1 = (w1 >> (i1 & 31u)) & 1u;
    }

    // Readout: out[m, o] = sum_j rf[m,j] * roW[o,j] + rob[o]
    sh_bits[t]       = (float)b0;
    sh_bits[t + 128] = (float)b1;
    __syncthreads();

    if (t < NOUT) {
        float acc = rob[t];
        const float* wrow = roW + t * RNODES;
#pragma unroll 8
        for (int j = 0; j < RNODES; j++)
            acc += sh_bits[j] * wrow[j];
        out[sid * NOUT + t] = acc;
    }
}

extern "C" void kernel_launch(void* const* d_in, const int* in_sizes, int n_in,
                              void* d_out, int out_size) {
    const void* x       = d_in[0];                   // bool [512,512,4,8] (dtype-detected)
    const int*  innod   = (const int*)d_in[1];       // int32 [32]
    const int*  lut     = (const int*)d_in[2];       // int32 [256, 262144]
    const void* W       = d_in[3];                   // bool [256,256]
    const int*  primes  = (const int*)d_in[4];       // int32 [256]
    const void* initres = d_in[5];                   // bool [256]
    const float* roW    = (const float*)d_in[6];     // f32 [10,256]
    const float* rob    = (const float*)d_in[7];     // f32 [10]
    float* out = (float*)d_out;                      // f32 [512,10]

    detect_kernel<<<1, 32>>>((const uint32_t*)x);
    pack_lut_kernel<<<8192, 256>>>(lut);             // 268 MB stream
    pack_x_kernel<<<1024, 256>>>(x);
    prep_small_kernel<<<(SEC_MISC + TA_N + TB_N + TT_N + 255) / 256, 256>>>(
        innod, initres, W, primes);
    prep2_kernel<<<(TAB13_ROWS * 128 + 255) / 256, 256>>>();
    reservoir_kernel<<<NSAMP, 128>>>(roW, rob, out);
}